// round 13
// baseline (speedup 1.0000x reference)
#include <cuda_runtime.h>
#include <cuda_fp16.h>
#include <math.h>
#include <cstdint>

// Problem constants
#define NB    16
#define NPTS  4096
#define MPTS  1024
#define CH2   256
#define CH1   128
#define OUT1  256
#define OUT2  256
#define LDA_W1 384

// ---- scratch ----
__device__ int    g_idx[NB * NPTS * 3];
__device__ float  g_wgt[NB * NPTS * 3];
__device__ float  g_Tt [NB * MPTS * OUT1];    // T transposed [b][m][o], fp32 (gather src)
__device__ __half g_W1h[OUT1 * LDA_W1];
__device__ __half g_W2h[OUT2 * OUT1];
__device__ __half g_p1h[NB * CH1 * NPTS];
__device__ __half g_p2h[NB * CH2 * MPTS];

// ===========================================================================
__device__ __forceinline__ uint32_t smem_u32(const void* p) {
    uint32_t a;
    asm("{ .reg .u64 t; cvta.to.shared.u64 t, %1; cvt.u32.u64 %0, t; }" : "=r"(a) : "l"(p));
    return a;
}
__device__ __forceinline__ void cp16(void* dst, const void* src) {
    asm volatile("cp.async.ca.shared.global [%0], [%1], 16;"
                 :: "r"(smem_u32(dst)), "l"(src));
}
__device__ __forceinline__ void ldsm_x4(uint32_t addr, uint32_t& r0, uint32_t& r1,
                                        uint32_t& r2, uint32_t& r3) {
    asm volatile("ldmatrix.sync.aligned.m8n8.x4.shared.b16 {%0,%1,%2,%3}, [%4];"
                 : "=r"(r0), "=r"(r1), "=r"(r2), "=r"(r3) : "r"(addr));
}
__device__ __forceinline__ void ldsm_x4t(uint32_t addr, uint32_t& r0, uint32_t& r1,
                                         uint32_t& r2, uint32_t& r3) {
    asm volatile("ldmatrix.sync.aligned.m8n8.x4.trans.shared.b16 {%0,%1,%2,%3}, [%4];"
                 : "=r"(r0), "=r"(r1), "=r"(r2), "=r"(r3) : "r"(addr));
}
#define MMA_F16(C, A, B) \
    asm volatile( \
        "mma.sync.aligned.m16n8k16.row.col.f32.f16.f16.f32 " \
        "{%0,%1,%2,%3}, {%4,%5,%6,%7}, {%8,%9}, {%0,%1,%2,%3};" \
        : "+f"((C)[0]), "+f"((C)[1]), "+f"((C)[2]), "+f"((C)[3]) \
        : "r"((A)[0]), "r"((A)[1]), "r"((A)[2]), "r"((A)[3]), \
          "r"((B)[0]), "r"((B)[1]))

// ===========================================================================
// Kernel A (merged): blocks [0,256) = three_nn ; blocks [256,512) = fp32->fp16
// ===========================================================================
__global__ __launch_bounds__(256)
void prep_kernel(const float* __restrict__ xyz1, const float* __restrict__ xyz2,
                 const float* __restrict__ W1,  const float* __restrict__ W2,
                 const float* __restrict__ p1,  const float* __restrict__ p2)
{
    __shared__ float4 s_p2[MPTS];   // (x, y, z, |p|^2)

    const int blk = blockIdx.x;
    const int tid = threadIdx.x;

    if (blk >= 256) {
        const int idx0   = (blk - 256) * 256 + tid;
        const int stride = 256 * 256;
        auto conv = [&](const float* __restrict__ src, __half* __restrict__ dst, int n4) {
            for (int i = idx0; i < n4; i += stride) {
                float4 v = reinterpret_cast<const float4*>(src)[i];
                reinterpret_cast<__half2*>(dst)[2 * i + 0] = __floats2half2_rn(v.x, v.y);
                reinterpret_cast<__half2*>(dst)[2 * i + 1] = __floats2half2_rn(v.z, v.w);
            }
        };
        conv(W1, g_W1h, OUT1 * LDA_W1 / 4);
        conv(W2, g_W2h, OUT2 * OUT1 / 4);
        conv(p1, g_p1h, NB * CH1 * NPTS / 4);
        conv(p2, g_p2h, NB * CH2 * MPTS / 4);
        return;
    }

    const int b    = blk >> 4;
    const int nblk = blk & 15;
    const float* x2 = xyz2 + (size_t)b * 3 * MPTS;
    for (int i = tid; i < MPTS; i += 256) {
        float xv = x2[i], yv = x2[MPTS + i], zv = x2[2 * MPTS + i];
        s_p2[i] = make_float4(xv, yv, zv, xv * xv + yv * yv + zv * zv);
    }
    __syncthreads();

    const int n = nblk * 256 + tid;
    const float* x1 = xyz1 + (size_t)b * 3 * NPTS;
    const float px = x1[n], py = x1[NPTS + n], pz = x1[2 * NPTS + n];
    const float sq1 = px * px + py * py + pz * pz;

    float d0 = 1e30f, d1 = 1e30f, d2 = 1e30f;
    int   i0 = 0, i1 = 0, i2 = 0;

    #pragma unroll 8
    for (int m = 0; m < MPTS; m++) {
        float4 p = s_p2[m];
        float inner = fmaf(px, p.x, fmaf(py, p.y, pz * p.z));
        float d = fmaf(-2.0f, inner, sq1 + p.w);
        if (d < d2) {
            if (d < d1) {
                d2 = d1; i2 = i1;
                if (d < d0) { d1 = d0; i1 = i0; d0 = d; i0 = m; }
                else        { d1 = d;  i1 = m; }
            } else { d2 = d; i2 = m; }
        }
    }

    float r0 = 1.0f / fmaxf(sqrtf(fmaxf(d0, 1e-20f)), 1e-10f);
    float r1 = 1.0f / fmaxf(sqrtf(fmaxf(d1, 1e-20f)), 1e-10f);
    float r2 = 1.0f / fmaxf(sqrtf(fmaxf(d2, 1e-20f)), 1e-10f);
    float inv = 1.0f / (r0 + r1 + r2);

    const int base = (b * NPTS + n) * 3;
    g_idx[base + 0] = i0; g_idx[base + 1] = i1; g_idx[base + 2] = i2;
    g_wgt[base + 0] = r0 * inv; g_wgt[base + 1] = r1 * inv; g_wgt[base + 2] = r2 * inv;
}

// ===========================================================================
// Shared tiling constants
// ===========================================================================
#define BK    32
#define ASTR  40     // halves per As row (32 + 8 pad)
#define BSTR  136    // halves per Bs/Y row (128 + 8 pad)
#define AS_BYTES   (2 * 128 * ASTR * 2)      // 20480
#define BS_BYTES   (2 * BK * BSTR * 2)       // 17408
#define Y_BYTES    (256 * BSTR * 2)          // 69632
#define FUSED_DYN  (AS_BYTES + BS_BYTES + Y_BYTES)   // 107520

// ===========================================================================
// Kernel B: Tt = (W1h[:, :256] @ p2h)^T  (fp32 out) — standalone, static smem
// ===========================================================================
__global__ __launch_bounds__(256, 2)
void gemm_t(void)
{
    constexpr int K = 256, NC = K / BK, LDA = LDA_W1, LDX = MPTS;

    __shared__ __align__(16) __half As[2][128][ASTR];
    __shared__ __align__(16) __half Bs[2][BK][BSTR];

    const int b     = blockIdx.z;
    const int nBase = blockIdx.x * 128;
    const int oBase = blockIdx.y * 128;
    const int tid   = threadIdx.x;
    const int wid   = tid >> 5;
    const int lane  = tid & 31;
    const int g     = lane >> 2;
    const int tc    = lane & 3;
    const int oW    = (wid >> 2) * 64;
    const int nW    = (wid & 3) * 32;

    const __half* Xb = g_p2h + (size_t)b * CH2 * MPTS;

    const int arow = tid & 127;
    const int akc0 = tid >> 7;
    const int bk0  = tid >> 4;
    const int bn8  = tid & 15;

    auto prefetch = [&](int c) {
        const int buf = c & 1;
        const int k0  = c * BK;
        const __half* ap = &g_W1h[(size_t)(oBase + arow) * LDA + k0];
        cp16(&As[buf][arow][8 * akc0],       ap + 8 * akc0);
        cp16(&As[buf][arow][8 * (akc0 + 2)], ap + 8 * (akc0 + 2));
        const __half* bp = &Xb[(size_t)k0 * LDX + nBase + 8 * bn8];
        cp16(&Bs[buf][bk0     ][8 * bn8], bp + (size_t)bk0 * LDX);
        cp16(&Bs[buf][bk0 + 16][8 * bn8], bp + (size_t)(bk0 + 16) * LDX);
        asm volatile("cp.async.commit_group;" ::: "memory");
    };

    const int lm = lane >> 3;
    const int lr = lane & 7;
    uint32_t aoff[4];
    #pragma unroll
    for (int mi = 0; mi < 4; mi++)
        aoff[mi] = ((oW + mi * 16 + lr + 8 * (lm & 1)) * ASTR + 8 * (lm >> 1)) * 2;
    uint32_t boff[2];
    #pragma unroll
    for (int pr = 0; pr < 2; pr++)
        boff[pr] = ((lr + 8 * (lm & 1)) * BSTR + nW + pr * 16 + 8 * (lm >> 1)) * 2;

    const uint32_t as_base = smem_u32(&As[0][0][0]);
    const uint32_t bs_base = smem_u32(&Bs[0][0][0]);
    constexpr uint32_t AS_BUF = 128 * ASTR * 2;
    constexpr uint32_t BS_BUF = BK * BSTR * 2;

    float c[4][4][4];
    #pragma unroll
    for (int mi = 0; mi < 4; mi++)
        #pragma unroll
        for (int ni = 0; ni < 4; ni++)
            #pragma unroll
            for (int q = 0; q < 4; q++) c[mi][ni][q] = 0.0f;

    prefetch(0);
    asm volatile("cp.async.wait_group 0;" ::: "memory");
    __syncthreads();

    for (int cc = 0; cc < NC; cc++) {
        const uint32_t asb = as_base + (cc & 1) * AS_BUF;
        const uint32_t bsb = bs_base + (cc & 1) * BS_BUF;
        if (cc + 1 < NC) prefetch(cc + 1);

        #pragma unroll
        for (int kk = 0; kk < BK; kk += 16) {
            uint32_t a[4][4];
            #pragma unroll
            for (int mi = 0; mi < 4; mi++)
                ldsm_x4(asb + aoff[mi] + kk * 2, a[mi][0], a[mi][1], a[mi][2], a[mi][3]);
            uint32_t bb[4][2];
            ldsm_x4t(bsb + boff[0] + kk * (BSTR * 2), bb[0][0], bb[0][1], bb[1][0], bb[1][1]);
            ldsm_x4t(bsb + boff[1] + kk * (BSTR * 2), bb[2][0], bb[2][1], bb[3][0], bb[3][1]);
            #pragma unroll
            for (int mi = 0; mi < 4; mi++)
                #pragma unroll
                for (int ni = 0; ni < 4; ni++)
                    MMA_F16(c[mi][ni], a[mi], bb[ni]);
        }

        asm volatile("cp.async.wait_group 0;" ::: "memory");
        __syncthreads();
    }

    float* Cb = g_Tt + (size_t)b * MPTS * OUT1;
    #pragma unroll
    for (int ni = 0; ni < 4; ni++) {
        #pragma unroll
        for (int t = 0; t < 2; t++) {
            int m = nBase + nW + ni * 8 + tc * 2 + t;
            float* mrow = Cb + (size_t)m * OUT1;
            #pragma unroll
            for (int mi = 0; mi < 4; mi++) {
                #pragma unroll
                for (int h = 0; h < 2; h++) {
                    int o = oBase + oW + mi * 16 + g + h * 8;
                    mrow[o] = c[mi][ni][h * 2 + t];
                }
            }
        }
    }
}

// ===========================================================================
// Kernel C (FUSED layer1+layer2): one CTA owns a 128-n block.
// Phase 1 (x2 o1-halves): y1 = relu(W1b @ p1 + b1 + gather(Tt)) -> Y smem fp16
// Phase 2 (x2 o2-halves): out = relu(W2 @ Y + b2) -> global fp32
// Y[256][136] fp16 in dynamic smem; phase 2 has NO B-side global traffic.
// ===========================================================================
extern __shared__ __align__(16) char s_dyn[];

__global__ __launch_bounds__(256, 2)
void gemm_fused(const float* __restrict__ b1, const float* __restrict__ b2,
                float* __restrict__ out)
{
    __half (*As)[128][ASTR] = reinterpret_cast<__half(*)[128][ASTR]>(s_dyn);
    __half (*Bs)[BK][BSTR]  = reinterpret_cast<__half(*)[BK][BSTR]>(s_dyn + AS_BYTES);
    __half* Y               = reinterpret_cast<__half*>(s_dyn + AS_BYTES + BS_BYTES);
    __shared__ int   s_j[128 * 3];
    __shared__ float s_w[128 * 3];

    const int b     = blockIdx.z;
    const int nBase = blockIdx.x * 128;
    const int tid   = threadIdx.x;
    const int wid   = tid >> 5;
    const int lane  = tid & 31;
    const int g     = lane >> 2;
    const int tc    = lane & 3;
    const int oW    = (wid >> 2) * 64;
    const int nW    = (wid & 3) * 32;

    // metadata preload (visibility via first __syncthreads)
    {
        const int*   gi = g_idx + ((size_t)b * NPTS + nBase) * 3;
        const float* gw = g_wgt + ((size_t)b * NPTS + nBase) * 3;
        for (int i = tid; i < 384; i += 256) { s_j[i] = gi[i]; s_w[i] = gw[i]; }
    }

    const int arow = tid & 127;
    const int akc0 = tid >> 7;
    const int bk0  = tid >> 4;
    const int bn8  = tid & 15;

    const int lm = lane >> 3;
    const int lr = lane & 7;
    uint32_t aoff[4];
    #pragma unroll
    for (int mi = 0; mi < 4; mi++)
        aoff[mi] = ((oW + mi * 16 + lr + 8 * (lm & 1)) * ASTR + 8 * (lm >> 1)) * 2;
    uint32_t boff[2];
    #pragma unroll
    for (int pr = 0; pr < 2; pr++)
        boff[pr] = ((lr + 8 * (lm & 1)) * BSTR + nW + pr * 16 + 8 * (lm >> 1)) * 2;

    const uint32_t as_base = smem_u32(&As[0][0][0]);
    const uint32_t bs_base = smem_u32(&Bs[0][0][0]);
    const uint32_t y_base  = smem_u32(Y);
    constexpr uint32_t AS_BUF = 128 * ASTR * 2;
    constexpr uint32_t BS_BUF = BK * BSTR * 2;

    const float*  Tb  = g_Tt + (size_t)b * MPTS * OUT1;
    const __half* p1b = g_p1h + (size_t)b * CH1 * NPTS;

    // ================= PHASE 1: two o1-halves, K=128 =================
    #pragma unroll 1
    for (int h1 = 0; h1 < 2; h1++) {
        const int o1Base = h1 * 128;

        auto prefetch1 = [&](int c) {
            const int buf = c & 1;
            const int k0  = c * BK;
            const __half* ap = &g_W1h[(size_t)(o1Base + arow) * LDA_W1 + 256 + k0];
            cp16(&As[buf][arow][8 * akc0],       ap + 8 * akc0);
            cp16(&As[buf][arow][8 * (akc0 + 2)], ap + 8 * (akc0 + 2));
            const __half* bp = &p1b[(size_t)k0 * NPTS + nBase + 8 * bn8];
            cp16(&Bs[buf][bk0     ][8 * bn8], bp + (size_t)bk0 * NPTS);
            cp16(&Bs[buf][bk0 + 16][8 * bn8], bp + (size_t)(bk0 + 16) * NPTS);
            asm volatile("cp.async.commit_group;" ::: "memory");
        };

        float c1[4][4][4];
        #pragma unroll
        for (int mi = 0; mi < 4; mi++)
            #pragma unroll
            for (int ni = 0; ni < 4; ni++)
                #pragma unroll
                for (int q = 0; q < 4; q++) c1[mi][ni][q] = 0.0f;

        prefetch1(0);
        asm volatile("cp.async.wait_group 0;" ::: "memory");
        __syncthreads();

        #pragma unroll 1
        for (int cc = 0; cc < 4; cc++) {
            const uint32_t asb = as_base + (cc & 1) * AS_BUF;
            const uint32_t bsb = bs_base + (cc & 1) * BS_BUF;
            if (cc + 1 < 4) prefetch1(cc + 1);

            #pragma unroll
            for (int kk = 0; kk < BK; kk += 16) {
                uint32_t a[4][4];
                #pragma unroll
                for (int mi = 0; mi < 4; mi++)
                    ldsm_x4(asb + aoff[mi] + kk * 2, a[mi][0], a[mi][1], a[mi][2], a[mi][3]);
                uint32_t bb[4][2];
                ldsm_x4t(bsb + boff[0] + kk * (BSTR * 2), bb[0][0], bb[0][1], bb[1][0], bb[1][1]);
                ldsm_x4t(bsb + boff[1] + kk * (BSTR * 2), bb[2][0], bb[2][1], bb[3][0], bb[3][1]);
                #pragma unroll
                for (int mi = 0; mi < 4; mi++)
                    #pragma unroll
                    for (int ni = 0; ni < 4; ni++)
                        MMA_F16(c1[mi][ni], a[mi], bb[ni]);
            }

            // interleaved scattered gather for ni group (cc+3)%4
            {
                const int gni = (cc + 3) & 3;
                #pragma unroll
                for (int t = 0; t < 2; t++) {
                    const int ncta = nW + gni * 8 + tc * 2 + t;
                    const int j0 = s_j[ncta * 3 + 0];
                    const int j1 = s_j[ncta * 3 + 1];
                    const int j2 = s_j[ncta * 3 + 2];
                    const float w0 = s_w[ncta * 3 + 0];
                    const float w1 = s_w[ncta * 3 + 1];
                    const float w2 = s_w[ncta * 3 + 2];
                    const float* r0 = Tb + (size_t)j0 * OUT1 + o1Base + oW;
                    const float* r1 = Tb + (size_t)j1 * OUT1 + o1Base + oW;
                    const float* r2 = Tb + (size_t)j2 * OUT1 + o1Base + oW;
                    #pragma unroll
                    for (int mi = 0; mi < 4; mi++) {
                        #pragma unroll
                        for (int h = 0; h < 2; h++) {
                            const int ol = mi * 16 + g + h * 8;
                            c1[mi][gni][h * 2 + t] +=
                                w0 * __ldg(&r0[ol]) + w1 * __ldg(&r1[ol]) + w2 * __ldg(&r2[ol]);
                        }
                    }
                }
            }

            asm volatile("cp.async.wait_group 0;" ::: "memory");
            __syncthreads();
        }

        // bias + relu + fp16 store into Y smem (conflict-free: bank = 4g+tc)
        #pragma unroll
        for (int mi = 0; mi < 4; mi++) {
            #pragma unroll
            for (int h = 0; h < 2; h++) {
                int o = o1Base + oW + mi * 16 + g + h * 8;   // y1 row = phase-2 k
                float bv = b1[o];
                __half* yrow = Y + (size_t)o * BSTR;
                #pragma unroll
                for (int ni = 0; ni < 4; ni++) {
                    int n = nW + ni * 8 + tc * 2;
                    float v0 = fmaxf(c1[mi][ni][0 + h * 2] + bv, 0.0f);
                    float v1 = fmaxf(c1[mi][ni][1 + h * 2] + bv, 0.0f);
                    *reinterpret_cast<__half2*>(&yrow[n]) = __floats2half2_rn(v0, v1);
                }
            }
        }
        __syncthreads();
    }

    // ================= PHASE 2: two o2-halves, K=256 from Y =================
    #pragma unroll 1
    for (int h2 = 0; h2 < 2; h2++) {
        const int o2Base = h2 * 128;

        auto prefetch2 = [&](int c) {
            const int buf = c & 1;
            const int k0  = c * BK;
            const __half* ap = &g_W2h[(size_t)(o2Base + arow) * OUT1 + k0];
            cp16(&As[buf][arow][8 * akc0],       ap + 8 * akc0);
            cp16(&As[buf][arow][8 * (akc0 + 2)], ap + 8 * (akc0 + 2));
            asm volatile("cp.async.commit_group;" ::: "memory");
        };

        float c2[4][4][4];
        #pragma unroll
        for (int mi = 0; mi < 4; mi++)
            #pragma unroll
            for (int ni = 0; ni < 4; ni++)
                #pragma unroll
                for (int q = 0; q < 4; q++) c2[mi][ni][q] = 0.0f;

        prefetch2(0);
        asm volatile("cp.async.wait_group 0;" ::: "memory");
        __syncthreads();

        #pragma unroll 1
        for (int cc = 0; cc < 8; cc++) {
            const uint32_t asb = as_base + (cc & 1) * AS_BUF;
            const uint32_t ybk = y_base + cc * (BK * BSTR * 2);   // Y rows cc*32..
            if (cc + 1 < 8) prefetch2(cc + 1);

            #pragma unroll
            for (int kk = 0; kk < BK; kk += 16) {
                uint32_t a[4][4];
                #pragma unroll
                for (int mi = 0; mi < 4; mi++)
                    ldsm_x4(asb + aoff[mi] + kk * 2, a[mi][0], a[mi][1], a[mi][2], a[mi][3]);
                uint32_t bb[4][2];
                ldsm_x4t(ybk + boff[0] + kk * (BSTR * 2), bb[0][0], bb[0][1], bb[1][0], bb[1][1]);
                ldsm_x4t(ybk + boff[1] + kk * (BSTR * 2), bb[2][0], bb[2][1], bb[3][0], bb[3][1]);
                #pragma unroll
                for (int mi = 0; mi < 4; mi++)
                    #pragma unroll
                    for (int ni = 0; ni < 4; ni++)
                        MMA_F16(c2[mi][ni], a[mi], bb[ni]);
            }

            asm volatile("cp.async.wait_group 0;" ::: "memory");
            __syncthreads();
        }

        // epilogue: bias + relu -> global fp32
        float* Cb = out + (size_t)b * OUT2 * NPTS;
        #pragma unroll
        for (int mi = 0; mi < 4; mi++) {
            #pragma unroll
            for (int h = 0; h < 2; h++) {
                int o = o2Base + oW + mi * 16 + g + h * 8;
                float bv = b2[o];
                float* orow = Cb + (size_t)o * NPTS + nBase;
                #pragma unroll
                for (int ni = 0; ni < 4; ni++) {
                    int n = nW + ni * 8 + tc * 2;
                    float v0 = fmaxf(c2[mi][ni][0 + h * 2] + bv, 0.0f);
                    float v1 = fmaxf(c2[mi][ni][1 + h * 2] + bv, 0.0f);
                    *reinterpret_cast<float2*>(&orow[n]) = make_float2(v0, v1);
                }
            }
        }
        __syncthreads();
    }
}

// ===========================================================================
extern "C" void kernel_launch(void* const* d_in, const int* in_sizes, int n_in,
                              void* d_out, int out_size)
{
    const float* xyz1    = (const float*)d_in[0];
    const float* xyz2    = (const float*)d_in[1];
    const float* points1 = (const float*)d_in[2];
    const float* points2 = (const float*)d_in[3];
    const float* W1      = (const float*)d_in[4];
    const float* b1      = (const float*)d_in[5];
    const float* W2      = (const float*)d_in[6];
    const float* b2      = (const float*)d_in[7];
    float*       out     = (float*)d_out;

    cudaFuncSetAttribute(gemm_fused,
                         cudaFuncAttributeMaxDynamicSharedMemorySize, FUSED_DYN);

    // three_nn + fp16 conversion, overlapped
    prep_kernel<<<512, 256>>>(xyz1, xyz2, W1, W2, points1, points2);

    // Tt = (W1[:, :256] @ points2)^T  (fp32)
    gemm_t<<<dim3(MPTS / 128, OUT1 / 128, NB), 256>>>();

    // fused: y1 (smem) -> out
    gemm_fused<<<dim3(NPTS / 128, 1, NB), 256, FUSED_DYN>>>(b1, b2, out);
}